// round 9
// baseline (speedup 1.0000x reference)
#include <cuda_runtime.h>
#include <cuda_bf16.h>
#include <cstdint>

#define NN 50000
#define EE 400000
#define HH 128
#define DD 15
#define GG 256

// ---------------- device scratch (no allocations allowed) ----------------
__device__ __align__(16) float g_bufA[(size_t)EE * HH];
__device__ __align__(16) float g_bufB[(size_t)EE * HH];
__device__ __align__(16) float g_amsg[(size_t)NN * HH];
// conv weights packed: [d][n][pair] -> uint2{ (h(2p),h(2p+1)) , (l(2p),l(2p+1)) }
__device__ __align__(16) uint2 g_Wpk[DD * HH * 64];
// edge-init weights packed likewise: [n][pair(32)] over K=64 (61 + 3 zero pad)
__device__ __align__(16) uint2 g_EiPk[HH * 32];
__device__ __align__(16) float g_alpha[DD * HH];
__device__ __align__(16) float g_beta[DD * HH];
__device__ int g_cnt[NN];
__device__ int g_rowptr[NN + 1];
__device__ int g_cursor[NN];
__device__ int g_csr[EE];

// ---------------- helpers ----------------
__device__ __forceinline__ void bf16_split2(float v, __nv_bfloat16& h, __nv_bfloat16& l) {
    h = __float2bfloat16(v);
    l = __float2bfloat16(v - __bfloat162float(h));
}

__device__ __forceinline__ unsigned pack2(__nv_bfloat16 a, __nv_bfloat16 b) {
    __nv_bfloat162 t = __halves2bfloat162(a, b);
    return *reinterpret_cast<unsigned*>(&t);
}

#define MMA_BF16(c, a, b)                                                    \
    asm volatile(                                                            \
        "mma.sync.aligned.m16n8k16.row.col.f32.bf16.bf16.f32 "               \
        "{%0,%1,%2,%3},{%4,%5,%6,%7},{%8,%9},{%0,%1,%2,%3};"                 \
        : "+f"((c)[0]), "+f"((c)[1]), "+f"((c)[2]), "+f"((c)[3])             \
        : "r"((a)[0]), "r"((a)[1]), "r"((a)[2]), "r"((a)[3]),                \
          "r"((b)[0]), "r"((b)[1]))

#define LDS64(r0, r1, addr)                                                  \
    asm volatile("ld.shared.v2.u32 {%0,%1}, [%2];" : "=r"(r0), "=r"(r1) : "r"(addr))

// ---------------- CSR build (by col) ----------------
__global__ void k_zero_cnt() {
    int i = blockIdx.x * blockDim.x + threadIdx.x;
    if (i < NN) g_cnt[i] = 0;
}

__global__ void k_count(const int* __restrict__ col) {
    int e = blockIdx.x * blockDim.x + threadIdx.x;
    if (e < EE) atomicAdd(&g_cnt[col[e]], 1);
}

__global__ void k_scan() {
    __shared__ int sh[1024];
    int t = threadIdx.x;
    const int C = (NN + 1023) / 1024;
    int base = t * C;
    int s = 0;
    for (int j = 0; j < C; j++) {
        int i = base + j;
        if (i < NN) s += g_cnt[i];
    }
    sh[t] = s;
    __syncthreads();
    for (int off = 1; off < 1024; off <<= 1) {
        int v = (t >= off) ? sh[t - off] : 0;
        __syncthreads();
        sh[t] += v;
        __syncthreads();
    }
    int run = sh[t] - s;
    for (int j = 0; j < C; j++) {
        int i = base + j;
        if (i < NN) {
            g_rowptr[i] = run;
            g_cursor[i] = run;
            run += g_cnt[i];
        }
    }
    if (t == 0) g_rowptr[NN] = EE;
}

__global__ void k_scatter(const int* __restrict__ col) {
    int e = blockIdx.x * blockDim.x + threadIdx.x;
    if (e < EE) {
        int pos = atomicAdd(&g_cursor[col[e]], 1);
        g_csr[pos] = e;
    }
}

__global__ void k_sortcsr() {
    int i = blockIdx.x * blockDim.x + threadIdx.x;
    if (i >= NN) return;
    int s = g_rowptr[i], e = g_rowptr[i + 1];
    for (int a = s + 1; a < e; a++) {
        int v = g_csr[a];
        int b = a - 1;
        while (b >= s && g_csr[b] > v) { g_csr[b + 1] = g_csr[b]; b--; }
        g_csr[b + 1] = v;
    }
}

// ---------------- parameter prep ----------------
__global__ void k_prep_w(const float* __restrict__ W) {
    int idx = blockIdx.x * blockDim.x + threadIdx.x;
    if (idx >= DD * HH * 64) return;
    int p = idx & 63;
    int dn = idx >> 6;  // d*128+n
    const float* src = W + (size_t)dn * HH + 2 * p;
    __nv_bfloat16 h0, h1, l0, l1;
    bf16_split2(src[0], h0, l0);
    bf16_split2(src[1], h1, l1);
    g_Wpk[idx] = make_uint2(pack2(h0, h1), pack2(l0, l1));
}

__global__ void k_prep_wei(const float* __restrict__ W) {
    int idx = blockIdx.x * blockDim.x + threadIdx.x;
    if (idx >= HH * 32) return;
    int n = idx >> 5, p = idx & 31;
    int k0 = 2 * p;
    float v0 = (k0 < 61) ? W[n * 61 + k0] : 0.f;
    float v1 = (k0 + 1 < 61) ? W[n * 61 + k0 + 1] : 0.f;
    __nv_bfloat16 h0, h1, l0, l1;
    bf16_split2(v0, h0, l0);
    bf16_split2(v1, h1, l1);
    g_EiPk[idx] = make_uint2(pack2(h0, h1), pack2(l0, l1));
}

__global__ void k_prep_bn(const float* __restrict__ b, const float* __restrict__ gm,
                          const float* __restrict__ bt, const float* __restrict__ rm,
                          const float* __restrict__ rv) {
    int idx = blockIdx.x * blockDim.x + threadIdx.x;
    if (idx >= DD * HH) return;
    float al = gm[idx] * rsqrtf(rv[idx] + 1e-5f);
    g_alpha[idx] = al;
    g_beta[idx] = al * (b[idx] - rm[idx]) + bt[idx];
}

// ---------------- a_msg / h_node: warp-per-node CSR gather ----------------
__global__ __launch_bounds__(256) void k_amsg(int flip) {
    const float* __restrict__ src = flip ? g_bufB : g_bufA;
    int w = (blockIdx.x * 256 + threadIdx.x) >> 5;
    int lane = threadIdx.x & 31;
    if (w >= NN) return;
    int s = g_rowptr[w], e = g_rowptr[w + 1];
    float4 acc = make_float4(0.f, 0.f, 0.f, 0.f);
    for (int j = s; j < e; j++) {
        int ed = g_csr[j];
        float4 v = reinterpret_cast<const float4*>(src)[(size_t)ed * 32 + lane];
        acc.x += v.x; acc.y += v.y; acc.z += v.z; acc.w += v.w;
    }
    reinterpret_cast<float4*>(g_amsg)[(size_t)w * 32 + lane] = acc;
}

// ---------------- fused DMPNN layer GEMM ----------------
// M-tile 64 edges, N-tile 64 (2 halves), interleaved hi/lo limbs, 3 CTAs/SM
// dst[e] = 2*relu(alpha * ((a_msg[row[e]] - src[e^1]) @ W^T) + beta)
#define PAB 544  // bytes per row: 64 pairs * 8B + 32B pad -> 8-bank row shift
#define A_OFF 1024
#define B_OFF (A_OFF + 64 * PAB)
#define SMEM_GEMM (B_OFF + 64 * PAB)  // 70656

__global__ __launch_bounds__(256, 3) void k_gemm(int flip, int layer,
                                                 const int* __restrict__ row) {
    const float* __restrict__ src = flip ? g_bufB : g_bufA;
    float* __restrict__ dst = flip ? g_bufA : g_bufB;
    extern __shared__ __align__(16) char smg[];
    float* als = (float*)smg;         // 64 entries (this N-half)
    float* bes = als + 64;
    char* Asm = smg + A_OFF;
    char* Bsm = smg + B_OFF;

    int tid = threadIdx.x;
    int nh = blockIdx.x;              // N-half 0/1 (fast dim -> sibling CTAs adjacent)
    int e0 = blockIdx.y * 64;

    if (tid < 64) {
        als[tid] = g_alpha[layer * HH + nh * 64 + tid];
        bes[tid] = g_beta[layer * HH + nh * 64 + tid];
    }

    // B: copy packed weights for this N-half (64 rows x 32 uint4)
    {
        const uint4* wp = (const uint4*)(g_Wpk + (size_t)layer * HH * 64 + (size_t)nh * 64 * 64);
        for (int i = tid; i < 2048; i += 256) {
            int n = i >> 5, c = i & 31;
            *reinterpret_cast<uint4*>(Bsm + n * PAB + c * 16) = wp[i];
        }
    }

    // A: msg = a_msg[row[e]] - src[e^1]; pack [h01,l01,h23,l23] per float4
    for (int i = tid; i < 2048; i += 256) {
        int m = i >> 5, k4 = i & 31;
        int e = e0 + m;
        int r = __ldg(&row[e]);
        float4 am = reinterpret_cast<const float4*>(g_amsg)[(size_t)r * 32 + k4];
        float4 rv = reinterpret_cast<const float4*>(src)[((size_t)(e ^ 1)) * 32 + k4];
        float v0 = am.x - rv.x, v1 = am.y - rv.y, v2 = am.z - rv.z, v3 = am.w - rv.w;
        __nv_bfloat16 h0, h1, h2, h3, l0, l1, l2, l3;
        bf16_split2(v0, h0, l0);
        bf16_split2(v1, h1, l1);
        bf16_split2(v2, h2, l2);
        bf16_split2(v3, h3, l3);
        uint4 val = make_uint4(pack2(h0, h1), pack2(l0, l1), pack2(h2, h3), pack2(l2, l3));
        *reinterpret_cast<uint4*>(Asm + m * PAB + k4 * 16) = val;
    }
    __syncthreads();

    int lane = tid & 31, w = tid >> 5;
    int m0 = (w & 3) * 16, n0 = (w >> 2) * 32;
    int gid = lane >> 2, tg = lane & 3;

    unsigned aBase = (unsigned)__cvta_generic_to_shared(Asm + (m0 + gid) * PAB + tg * 8);
    unsigned bBase = (unsigned)__cvta_generic_to_shared(Bsm + (n0 + gid) * PAB + tg * 8);

    float acc[4][4];
#pragma unroll
    for (int nf = 0; nf < 4; nf++)
#pragma unroll
        for (int q = 0; q < 4; q++) acc[nf][q] = 0.f;

#pragma unroll 2
    for (int ks = 0; ks < 8; ks++) {
        unsigned koff = ks * 64;  // 8 pairs * 8B
        unsigned ah[4], al[4];
        {
            unsigned o = aBase + koff;
            LDS64(ah[0], al[0], o);
            LDS64(ah[2], al[2], o + 32);
            LDS64(ah[1], al[1], o + 8 * PAB);
            LDS64(ah[3], al[3], o + 8 * PAB + 32);
        }
        unsigned bh[4][2], bl[4][2];
#pragma unroll
        for (int nf = 0; nf < 4; nf++) {
            unsigned o = bBase + nf * (8 * PAB) + koff;
            LDS64(bh[nf][0], bl[nf][0], o);
            LDS64(bh[nf][1], bl[nf][1], o + 32);
        }
#pragma unroll
        for (int nf = 0; nf < 4; nf++) {
            MMA_BF16(acc[nf], ah, bh[nf]);
            MMA_BF16(acc[nf], ah, bl[nf]);
            MMA_BF16(acc[nf], al, bh[nf]);
        }
    }

    // epilogue: 2*relu(alpha*acc + beta)
#pragma unroll
    for (int nf = 0; nf < 4; nf++) {
        int cl = n0 + nf * 8 + 2 * tg;       // local col in [0,64)
        int gc = nh * 64 + cl;               // global col
        float2 a2 = *reinterpret_cast<const float2*>(&als[cl]);
        float2 b2 = *reinterpret_cast<const float2*>(&bes[cl]);
        int r0 = e0 + m0 + gid;
        float2 o0, o1;
        o0.x = 2.f * fmaxf(fmaf(a2.x, acc[nf][0], b2.x), 0.f);
        o0.y = 2.f * fmaxf(fmaf(a2.y, acc[nf][1], b2.y), 0.f);
        o1.x = 2.f * fmaxf(fmaf(a2.x, acc[nf][2], b2.x), 0.f);
        o1.y = 2.f * fmaxf(fmaf(a2.y, acc[nf][3], b2.y), 0.f);
        *reinterpret_cast<float2*>(&dst[(size_t)r0 * HH + gc]) = o0;
        *reinterpret_cast<float2*>(&dst[(size_t)(r0 + 8) * HH + gc]) = o1;
    }
}

// ---------------- edge init: bf16 2-limb, K=64 (61+pad), M64/N128 ----------------
// g_bufA[e] = relu([x[row[e]] | edge_attr[e] | 0] @ Wei^T + bei)
#define PEI 288  // 32 pairs * 8B + 32B pad -> 8-bank row shift
#define EA_OFF 1024
#define EB_OFF (EA_OFF + 64 * PEI)
#define SMEM_EI (EB_OFF + 128 * PEI)  // 56320

__global__ __launch_bounds__(256, 3) void k_edge_init(const float* __restrict__ x,
                                                      const float* __restrict__ eat,
                                                      const int* __restrict__ row,
                                                      const float* __restrict__ bei) {
    extern __shared__ __align__(16) char sme[];
    float* bes = (float*)sme;  // 128 bias
    char* Asm = sme + EA_OFF;
    char* Bsm = sme + EB_OFF;

    int tid = threadIdx.x;
    int e0 = blockIdx.x * 64;

    if (tid < 128) bes[tid] = bei[tid];

    // B: 128 rows x 16 uint4 (32 pairs)
    {
        const uint4* wp = (const uint4*)g_EiPk;
        for (int i = tid; i < 2048; i += 256) {
            int n = i >> 4, c = i & 15;
            *reinterpret_cast<uint4*>(Bsm + n * PEI + c * 16) = wp[i];
        }
    }

    // A: feats = [x[row[e]](48) | eat[e](13) | 0(3)], packed hi/lo per pair
    for (int i = tid; i < 1024; i += 256) {
        int m = i >> 4, k4 = i & 15;
        int e = e0 + m;
        float4 v;
        if (k4 < 12) {
            int r = __ldg(&row[e]);
            v = *reinterpret_cast<const float4*>(&x[(size_t)r * 48 + (k4 << 2)]);
        } else {
            int kb = k4 << 2;
            float t[4];
#pragma unroll
            for (int j = 0; j < 4; j++) {
                int kk = kb + j;
                t[j] = (kk < 61) ? eat[(size_t)e * 13 + (kk - 48)] : 0.f;
            }
            v = make_float4(t[0], t[1], t[2], t[3]);
        }
        __nv_bfloat16 h0, h1, h2, h3, l0, l1, l2, l3;
        bf16_split2(v.x, h0, l0);
        bf16_split2(v.y, h1, l1);
        bf16_split2(v.z, h2, l2);
        bf16_split2(v.w, h3, l3);
        uint4 val = make_uint4(pack2(h0, h1), pack2(l0, l1), pack2(h2, h3), pack2(l2, l3));
        *reinterpret_cast<uint4*>(Asm + m * PEI + k4 * 16) = val;
    }
    __syncthreads();

    int lane = tid & 31, w = tid >> 5;
    int m0 = (w >> 2) * 32, n0 = (w & 3) * 32;
    int gid = lane >> 2, tg = lane & 3;

    unsigned aBase = (unsigned)__cvta_generic_to_shared(Asm + (m0 + gid) * PEI + tg * 8);
    unsigned bBase = (unsigned)__cvta_generic_to_shared(Bsm + (n0 + gid) * PEI + tg * 8);

    float acc[2][4][4];
#pragma unroll
    for (int mf = 0; mf < 2; mf++)
#pragma unroll
        for (int nf = 0; nf < 4; nf++)
#pragma unroll
            for (int q = 0; q < 4; q++) acc[mf][nf][q] = 0.f;

#pragma unroll 2
    for (int ks = 0; ks < 4; ks++) {
        unsigned koff = ks * 64;
        unsigned ah[2][4], al[2][4];
#pragma unroll
        for (int mf = 0; mf < 2; mf++) {
            unsigned o = aBase + mf * (16 * PEI) + koff;
            LDS64(ah[mf][0], al[mf][0], o);
            LDS64(ah[mf][2], al[mf][2], o + 32);
            LDS64(ah[mf][1], al[mf][1], o + 8 * PEI);
            LDS64(ah[mf][3], al[mf][3], o + 8 * PEI + 32);
        }
        unsigned bh[4][2], bl[4][2];
#pragma unroll
        for (int nf = 0; nf < 4; nf++) {
            unsigned o = bBase + nf * (8 * PEI) + koff;
            LDS64(bh[nf][0], bl[nf][0], o);
            LDS64(bh[nf][1], bl[nf][1], o + 32);
        }
#pragma unroll
        for (int mf = 0; mf < 2; mf++)
#pragma unroll
            for (int nf = 0; nf < 4; nf++) {
                MMA_BF16(acc[mf][nf], ah[mf], bh[nf]);
                MMA_BF16(acc[mf][nf], ah[mf], bl[nf]);
                MMA_BF16(acc[mf][nf], al[mf], bh[nf]);
            }
    }

    // epilogue: relu(acc + bias)
#pragma unroll
    for (int nf = 0; nf < 4; nf++) {
        int c = n0 + nf * 8 + 2 * tg;
        float2 b2 = *reinterpret_cast<const float2*>(&bes[c]);
#pragma unroll
        for (int mf = 0; mf < 2; mf++) {
            int r0 = e0 + m0 + mf * 16 + gid;
            float2 o0, o1;
            o0.x = fmaxf(acc[mf][nf][0] + b2.x, 0.f);
            o0.y = fmaxf(acc[mf][nf][1] + b2.y, 0.f);
            o1.x = fmaxf(acc[mf][nf][2] + b2.x, 0.f);
            o1.y = fmaxf(acc[mf][nf][3] + b2.y, 0.f);
            *reinterpret_cast<float2*>(&g_bufA[(size_t)r0 * HH + c]) = o0;
            *reinterpret_cast<float2*>(&g_bufA[(size_t)(r0 + 8) * HH + c]) = o1;
        }
    }
}

// ---------------- pooling + FFN + sigmoid ----------------
__global__ __launch_bounds__(256) void k_pool(const int* __restrict__ batch,
                                              const float* __restrict__ fW,
                                              const float* __restrict__ fb,
                                              float* __restrict__ out) {
    int g = (blockIdx.x * 256 + threadIdx.x) >> 5;
    int lane = threadIdx.x & 31;
    if (g >= GG) return;
    int s, e;
    {
        int lo = 0, hi = NN;
        while (lo < hi) { int mid = (lo + hi) >> 1; if (batch[mid] < g) lo = mid + 1; else hi = mid; }
        s = lo;
    }
    {
        int lo = s, hi = NN;
        while (lo < hi) { int mid = (lo + hi) >> 1; if (batch[mid] < g + 1) lo = mid + 1; else hi = mid; }
        e = lo;
    }
    float4 acc = make_float4(0.f, 0.f, 0.f, 0.f);
    for (int n = s; n < e; n++) {
        float4 v = reinterpret_cast<const float4*>(g_amsg)[(size_t)n * 32 + lane];
        acc.x += v.x; acc.y += v.y; acc.z += v.z; acc.w += v.w;
    }
    float4 w = reinterpret_cast<const float4*>(fW)[lane];
    float dot = acc.x * w.x + acc.y * w.y + acc.z * w.z + acc.w * w.w;
#pragma unroll
    for (int off = 16; off; off >>= 1) dot += __shfl_down_sync(0xffffffffu, dot, off);
    if (lane == 0) {
        int cnt = e - s;
        float c = (float)(cnt > 0 ? cnt : 1);
        float z = dot / c + fb[0];
        out[g] = 1.f / (1.f + expf(-z));
    }
}

// ---------------- launch ----------------
extern "C" void kernel_launch(void* const* d_in, const int* in_sizes, int n_in,
                              void* d_out, int out_size) {
    const float* x     = (const float*)d_in[0];
    const float* eat   = (const float*)d_in[1];
    const int*   eidx  = (const int*)d_in[2];
    const int*   batch = (const int*)d_in[3];
    const float* Wei   = (const float*)d_in[6];
    const float* bei   = (const float*)d_in[7];
    const float* convW = (const float*)d_in[8];
    const float* convb = (const float*)d_in[9];
    const float* gam   = (const float*)d_in[10];
    const float* bet   = (const float*)d_in[11];
    const float* rm    = (const float*)d_in[12];
    const float* rv    = (const float*)d_in[13];
    const float* fW    = (const float*)d_in[14];
    const float* fb    = (const float*)d_in[15];
    float* out = (float*)d_out;

    const int* row = eidx;
    const int* col = eidx + EE;

    cudaFuncSetAttribute(k_gemm, cudaFuncAttributeMaxDynamicSharedMemorySize, SMEM_GEMM);
    cudaFuncSetAttribute(k_edge_init, cudaFuncAttributeMaxDynamicSharedMemorySize, SMEM_EI);

    // CSR build (deterministic after sort)
    k_zero_cnt<<<(NN + 255) / 256, 256>>>();
    k_count<<<(EE + 255) / 256, 256>>>(col);
    k_scan<<<1, 1024>>>();
    k_scatter<<<(EE + 255) / 256, 256>>>(col);
    k_sortcsr<<<(NN + 255) / 256, 256>>>();

    // parameter prep
    k_prep_w<<<(DD * HH * 64 + 255) / 256, 256>>>(convW);
    k_prep_wei<<<(HH * 32 + 255) / 256, 256>>>(Wei);
    k_prep_bn<<<(DD * HH + 255) / 256, 256>>>(convb, gam, bet, rm, rv);

    // edge init -> bufA
    k_edge_init<<<EE / 64, 256, SMEM_EI>>>(x, eat, row, bei);

    // 15 DMPNN layers, ping-pong A<->B
    for (int d = 0; d < DD; d++) {
        int flip = d & 1;
        k_amsg<<<(NN * 32 + 255) / 256, 256>>>(flip);
        k_gemm<<<dim3(2, EE / 64), 256, SMEM_GEMM>>>(flip, d, row);
    }

    // final node aggregation from bufB, then pool+FFN
    k_amsg<<<(NN * 32 + 255) / 256, 256>>>(1);
    k_pool<<<(GG * 32 + 255) / 256, 256>>>(batch, fW, fb, out);
}

// round 10
// speedup vs baseline: 1.2359x; 1.2359x over previous
#include <cuda_runtime.h>
#include <cuda_bf16.h>
#include <cstdint>

#define NN 50000
#define EE 400000
#define HH 128
#define DD 15
#define GG 256

// ---------------- device scratch (no allocations allowed) ----------------
__device__ __align__(16) float g_bufA[(size_t)EE * HH];
__device__ __align__(16) float g_bufB[(size_t)EE * HH];
__device__ __align__(16) float g_amsg[(size_t)NN * HH];
// conv weights packed: [d][n][pair] -> uint2{ (h(2p),h(2p+1)) , (l(2p),l(2p+1)) }
__device__ __align__(16) uint2 g_Wpk[DD * HH * 64];
// edge-init weights packed likewise: [n][pair(32)] over K=64 (61 + 3 zero pad)
__device__ __align__(16) uint2 g_EiPk[HH * 32];
__device__ __align__(16) float g_alpha[DD * HH];
__device__ __align__(16) float g_beta[DD * HH];
__device__ int g_cnt[NN];
__device__ int g_rowptr[NN + 1];
__device__ int g_cursor[NN];
__device__ int g_csr[EE];

// ---------------- helpers ----------------
__device__ __forceinline__ void bf16_split2(float v, __nv_bfloat16& h, __nv_bfloat16& l) {
    h = __float2bfloat16(v);
    l = __float2bfloat16(v - __bfloat162float(h));
}

__device__ __forceinline__ unsigned pack2(__nv_bfloat16 a, __nv_bfloat16 b) {
    __nv_bfloat162 t = __halves2bfloat162(a, b);
    return *reinterpret_cast<unsigned*>(&t);
}

#define MMA_BF16(c, a, b)                                                    \
    asm volatile(                                                            \
        "mma.sync.aligned.m16n8k16.row.col.f32.bf16.bf16.f32 "               \
        "{%0,%1,%2,%3},{%4,%5,%6,%7},{%8,%9},{%0,%1,%2,%3};"                 \
        : "+f"((c)[0]), "+f"((c)[1]), "+f"((c)[2]), "+f"((c)[3])             \
        : "r"((a)[0]), "r"((a)[1]), "r"((a)[2]), "r"((a)[3]),                \
          "r"((b)[0]), "r"((b)[1]))

#define LDS64(r0, r1, addr)                                                  \
    asm volatile("ld.shared.v2.u32 {%0,%1}, [%2];" : "=r"(r0), "=r"(r1) : "r"(addr))

#define CP_ASYNC16(smem_u32, gptr)                                           \
    asm volatile("cp.async.cg.shared.global [%0], [%1], 16;" ::              \
                     "r"(smem_u32), "l"(gptr))
#define CP_ASYNC_WAIT_ALL()                                                  \
    do {                                                                     \
        asm volatile("cp.async.commit_group;");                              \
        asm volatile("cp.async.wait_group 0;");                              \
    } while (0)

// ---------------- CSR build (by col) ----------------
__global__ void k_zero_cnt() {
    int i = blockIdx.x * blockDim.x + threadIdx.x;
    if (i < NN) g_cnt[i] = 0;
}

__global__ void k_count(const int* __restrict__ col) {
    int e = blockIdx.x * blockDim.x + threadIdx.x;
    if (e < EE) atomicAdd(&g_cnt[col[e]], 1);
}

__global__ void k_scan() {
    __shared__ int sh[1024];
    int t = threadIdx.x;
    const int C = (NN + 1023) / 1024;
    int base = t * C;
    int s = 0;
    for (int j = 0; j < C; j++) {
        int i = base + j;
        if (i < NN) s += g_cnt[i];
    }
    sh[t] = s;
    __syncthreads();
    for (int off = 1; off < 1024; off <<= 1) {
        int v = (t >= off) ? sh[t - off] : 0;
        __syncthreads();
        sh[t] += v;
        __syncthreads();
    }
    int run = sh[t] - s;
    for (int j = 0; j < C; j++) {
        int i = base + j;
        if (i < NN) {
            g_rowptr[i] = run;
            g_cursor[i] = run;
            run += g_cnt[i];
        }
    }
    if (t == 0) g_rowptr[NN] = EE;
}

__global__ void k_scatter(const int* __restrict__ col) {
    int e = blockIdx.x * blockDim.x + threadIdx.x;
    if (e < EE) {
        int pos = atomicAdd(&g_cursor[col[e]], 1);
        g_csr[pos] = e;
    }
}

__global__ void k_sortcsr() {
    int i = blockIdx.x * blockDim.x + threadIdx.x;
    if (i >= NN) return;
    int s = g_rowptr[i], e = g_rowptr[i + 1];
    for (int a = s + 1; a < e; a++) {
        int v = g_csr[a];
        int b = a - 1;
        while (b >= s && g_csr[b] > v) { g_csr[b + 1] = g_csr[b]; b--; }
        g_csr[b + 1] = v;
    }
}

// ---------------- parameter prep ----------------
__global__ void k_prep_w(const float* __restrict__ W) {
    int idx = blockIdx.x * blockDim.x + threadIdx.x;
    if (idx >= DD * HH * 64) return;
    int p = idx & 63;
    int dn = idx >> 6;  // d*128+n
    const float* src = W + (size_t)dn * HH + 2 * p;
    __nv_bfloat16 h0, h1, l0, l1;
    bf16_split2(src[0], h0, l0);
    bf16_split2(src[1], h1, l1);
    g_Wpk[idx] = make_uint2(pack2(h0, h1), pack2(l0, l1));
}

__global__ void k_prep_wei(const float* __restrict__ W) {
    int idx = blockIdx.x * blockDim.x + threadIdx.x;
    if (idx >= HH * 32) return;
    int n = idx >> 5, p = idx & 31;
    int k0 = 2 * p;
    float v0 = (k0 < 61) ? W[n * 61 + k0] : 0.f;
    float v1 = (k0 + 1 < 61) ? W[n * 61 + k0 + 1] : 0.f;
    __nv_bfloat16 h0, h1, l0, l1;
    bf16_split2(v0, h0, l0);
    bf16_split2(v1, h1, l1);
    g_EiPk[idx] = make_uint2(pack2(h0, h1), pack2(l0, l1));
}

__global__ void k_prep_bn(const float* __restrict__ b, const float* __restrict__ gm,
                          const float* __restrict__ bt, const float* __restrict__ rm,
                          const float* __restrict__ rv) {
    int idx = blockIdx.x * blockDim.x + threadIdx.x;
    if (idx >= DD * HH) return;
    float al = gm[idx] * rsqrtf(rv[idx] + 1e-5f);
    g_alpha[idx] = al;
    g_beta[idx] = al * (b[idx] - rm[idx]) + bt[idx];
}

// ---------------- a_msg / h_node: warp-per-node CSR gather ----------------
__global__ __launch_bounds__(256) void k_amsg(int flip) {
    const float* __restrict__ src = flip ? g_bufB : g_bufA;
    int w = (blockIdx.x * 256 + threadIdx.x) >> 5;
    int lane = threadIdx.x & 31;
    if (w >= NN) return;
    int s = g_rowptr[w], e = g_rowptr[w + 1];
    float4 acc = make_float4(0.f, 0.f, 0.f, 0.f);
    for (int j = s; j < e; j++) {
        int ed = g_csr[j];
        float4 v = reinterpret_cast<const float4*>(src)[(size_t)ed * 32 + lane];
        acc.x += v.x; acc.y += v.y; acc.z += v.z; acc.w += v.w;
    }
    reinterpret_cast<float4*>(g_amsg)[(size_t)w * 32 + lane] = acc;
}

// ---------------- fused DMPNN layer GEMM (R7 config: M64/N128, 2 CTAs/SM) ----------------
// dst[e] = 2*relu(alpha * ((a_msg[row[e]] - src[e^1]) @ W^T) + beta)
#define PAB 544  // bytes per row: 64 pairs * 8B + 32B pad -> 8-bank row shift
#define A_OFF 1024
#define B_OFF (A_OFF + 64 * PAB)
#define SMEM_GEMM (B_OFF + 128 * PAB)

__global__ __launch_bounds__(256, 2) void k_gemm(int flip, int layer,
                                                 const int* __restrict__ row) {
    const float* __restrict__ src = flip ? g_bufB : g_bufA;
    float* __restrict__ dst = flip ? g_bufA : g_bufB;
    extern __shared__ __align__(16) char smg[];
    float* als = (float*)smg;
    float* bes = als + 128;
    char* Asm = smg + A_OFF;
    char* Bsm = smg + B_OFF;

    int tid = threadIdx.x;
    int e0 = blockIdx.x * 64;

    if (tid < 128) {
        als[tid] = g_alpha[layer * HH + tid];
        bes[tid] = g_beta[layer * HH + tid];
    }

    // B: async copy of packed weights (128 rows x 32 uint4), overlapped with A build
    {
        const uint4* wp = (const uint4*)(g_Wpk + (size_t)layer * HH * 64);
        unsigned bsh = (unsigned)__cvta_generic_to_shared(Bsm);
#pragma unroll
        for (int i = tid; i < 4096; i += 256) {
            int n = i >> 5, c = i & 31;
            CP_ASYNC16(bsh + n * PAB + c * 16, wp + i);
        }
    }

    // A: msg = a_msg[row[e]] - src[e^1]; pack [h01,l01,h23,l23] per float4
    for (int i = tid; i < 2048; i += 256) {
        int m = i >> 5, k4 = i & 31;
        int e = e0 + m;
        int r = __ldg(&row[e]);
        float4 am = reinterpret_cast<const float4*>(g_amsg)[(size_t)r * 32 + k4];
        float4 rv = reinterpret_cast<const float4*>(src)[((size_t)(e ^ 1)) * 32 + k4];
        float v0 = am.x - rv.x, v1 = am.y - rv.y, v2 = am.z - rv.z, v3 = am.w - rv.w;
        __nv_bfloat16 h0, h1, h2, h3, l0, l1, l2, l3;
        bf16_split2(v0, h0, l0);
        bf16_split2(v1, h1, l1);
        bf16_split2(v2, h2, l2);
        bf16_split2(v3, h3, l3);
        uint4 val = make_uint4(pack2(h0, h1), pack2(l0, l1), pack2(h2, h3), pack2(l2, l3));
        *reinterpret_cast<uint4*>(Asm + m * PAB + k4 * 16) = val;
    }
    CP_ASYNC_WAIT_ALL();
    __syncthreads();

    int lane = tid & 31, w = tid >> 5;
    int m0 = (w >> 2) * 32, n0 = (w & 3) * 32;
    int gid = lane >> 2, tg = lane & 3;

    unsigned aBase = (unsigned)__cvta_generic_to_shared(Asm + (m0 + gid) * PAB + tg * 8);
    unsigned bBase = (unsigned)__cvta_generic_to_shared(Bsm + (n0 + gid) * PAB + tg * 8);

    float acc[2][4][4];
#pragma unroll
    for (int mf = 0; mf < 2; mf++)
#pragma unroll
        for (int nf = 0; nf < 4; nf++)
#pragma unroll
            for (int q = 0; q < 4; q++) acc[mf][nf][q] = 0.f;

#pragma unroll 2
    for (int ks = 0; ks < 8; ks++) {
        unsigned koff = ks * 64;  // 8 pairs * 8B
        unsigned ah[2][4], al[2][4];
#pragma unroll
        for (int mf = 0; mf < 2; mf++) {
            unsigned o = aBase + mf * (16 * PAB) + koff;
            LDS64(ah[mf][0], al[mf][0], o);
            LDS64(ah[mf][2], al[mf][2], o + 32);
            LDS64(ah[mf][1], al[mf][1], o + 8 * PAB);
            LDS64(ah[mf][3], al[mf][3], o + 8 * PAB + 32);
        }
        unsigned bh[4][2], bl[4][2];
#pragma unroll
        for (int nf = 0; nf < 4; nf++) {
            unsigned o = bBase + nf * (8 * PAB) + koff;
            LDS64(bh[nf][0], bl[nf][0], o);
            LDS64(bh[nf][1], bl[nf][1], o + 32);
        }
#pragma unroll
        for (int mf = 0; mf < 2; mf++)
#pragma unroll
            for (int nf = 0; nf < 4; nf++) {
                MMA_BF16(acc[mf][nf], ah[mf], bh[nf]);
                MMA_BF16(acc[mf][nf], ah[mf], bl[nf]);
                MMA_BF16(acc[mf][nf], al[mf], bh[nf]);
            }
    }

    // epilogue: 2*relu(alpha*acc + beta)
#pragma unroll
    for (int nf = 0; nf < 4; nf++) {
        int c = n0 + nf * 8 + 2 * tg;
        float2 a2 = *reinterpret_cast<const float2*>(&als[c]);
        float2 b2 = *reinterpret_cast<const float2*>(&bes[c]);
#pragma unroll
        for (int mf = 0; mf < 2; mf++) {
            int r0 = e0 + m0 + mf * 16 + gid;
            float2 o0, o1;
            o0.x = 2.f * fmaxf(fmaf(a2.x, acc[mf][nf][0], b2.x), 0.f);
            o0.y = 2.f * fmaxf(fmaf(a2.y, acc[mf][nf][1], b2.y), 0.f);
            o1.x = 2.f * fmaxf(fmaf(a2.x, acc[mf][nf][2], b2.x), 0.f);
            o1.y = 2.f * fmaxf(fmaf(a2.y, acc[mf][nf][3], b2.y), 0.f);
            *reinterpret_cast<float2*>(&dst[(size_t)r0 * HH + c]) = o0;
            *reinterpret_cast<float2*>(&dst[(size_t)(r0 + 8) * HH + c]) = o1;
        }
    }
}

// ---------------- edge init: bf16 2-limb, K=64 (61+pad), M64/N128 ----------------
// g_bufA[e] = relu([x[row[e]] | edge_attr[e] | 0] @ Wei^T + bei)
#define PEI 288  // 32 pairs * 8B + 32B pad -> 8-bank row shift
#define EA_OFF 1024
#define EB_OFF (EA_OFF + 64 * PEI)
#define SMEM_EI (EB_OFF + 128 * PEI)  // 56320

__global__ __launch_bounds__(256, 3) void k_edge_init(const float* __restrict__ x,
                                                      const float* __restrict__ eat,
                                                      const int* __restrict__ row,
                                                      const float* __restrict__ bei) {
    extern __shared__ __align__(16) char sme[];
    float* bes = (float*)sme;  // 128 bias
    char* Asm = sme + EA_OFF;
    char* Bsm = sme + EB_OFF;

    int tid = threadIdx.x;
    int e0 = blockIdx.x * 64;

    if (tid < 128) bes[tid] = bei[tid];

    // B: async copy 128 rows x 16 uint4 (32 pairs)
    {
        const uint4* wp = (const uint4*)g_EiPk;
        unsigned bsh = (unsigned)__cvta_generic_to_shared(Bsm);
#pragma unroll
        for (int i = tid; i < 2048; i += 256) {
            int n = i >> 4, c = i & 15;
            CP_ASYNC16(bsh + n * PEI + c * 16, wp + i);
        }
    }

    // A: feats = [x[row[e]](48) | eat[e](13) | 0(3)], packed hi/lo per pair
    for (int i = tid; i < 1024; i += 256) {
        int m = i >> 4, k4 = i & 15;
        int e = e0 + m;
        float4 v;
        if (k4 < 12) {
            int r = __ldg(&row[e]);
            v = *reinterpret_cast<const float4*>(&x[(size_t)r * 48 + (k4 << 2)]);
        } else {
            int kb = k4 << 2;
            float t[4];
#pragma unroll
            for (int j = 0; j < 4; j++) {
                int kk = kb + j;
                t[j] = (kk < 61) ? eat[(size_t)e * 13 + (kk - 48)] : 0.f;
            }
            v = make_float4(t[0], t[1], t[2], t[3]);
        }
        __nv_bfloat16 h0, h1, h2, h3, l0, l1, l2, l3;
        bf16_split2(v.x, h0, l0);
        bf16_split2(v.y, h1, l1);
        bf16_split2(v.z, h2, l2);
        bf16_split2(v.w, h3, l3);
        uint4 val = make_uint4(pack2(h0, h1), pack2(l0, l1), pack2(h2, h3), pack2(l2, l3));
        *reinterpret_cast<uint4*>(Asm + m * PEI + k4 * 16) = val;
    }
    CP_ASYNC_WAIT_ALL();
    __syncthreads();

    int lane = tid & 31, w = tid >> 5;
    int m0 = (w >> 2) * 32, n0 = (w & 3) * 32;
    int gid = lane >> 2, tg = lane & 3;

    unsigned aBase = (unsigned)__cvta_generic_to_shared(Asm + (m0 + gid) * PEI + tg * 8);
    unsigned bBase = (unsigned)__cvta_generic_to_shared(Bsm + (n0 + gid) * PEI + tg * 8);

    float acc[2][4][4];
#pragma unroll
    for (int mf = 0; mf < 2; mf++)
#pragma unroll
        for (int nf = 0; nf < 4; nf++)
#pragma unroll
            for (int q = 0; q < 4; q++) acc[mf][nf][q] = 0.f;

#pragma unroll 2
    for (int ks = 0; ks < 4; ks++) {
        unsigned koff = ks * 64;
        unsigned ah[2][4], al[2][4];
#pragma unroll
        for (int mf = 0; mf < 2; mf++) {
            unsigned o = aBase + mf * (16 * PEI) + koff;
            LDS64(ah[mf][0], al[mf][0], o);
            LDS64(ah[mf][2], al[mf][2], o + 32);
            LDS64(ah[mf][1], al[mf][1], o + 8 * PEI);
            LDS64(ah[mf][3], al[mf][3], o + 8 * PEI + 32);
        }
        unsigned bh[4][2], bl[4][2];
#pragma unroll
        for (int nf = 0; nf < 4; nf++) {
            unsigned o = bBase + nf * (8 * PEI) + koff;
            LDS64(bh[nf][0], bl[nf][0], o);
            LDS64(bh[nf][1], bl[nf][1], o + 32);
        }
#pragma unroll
        for (int mf = 0; mf < 2; mf++)
#pragma unroll
            for (int nf = 0; nf < 4; nf++) {
                MMA_BF16(acc[mf][nf], ah[mf], bh[nf]);
                MMA_BF16(acc[mf][nf], ah[mf], bl[nf]);
                MMA_BF16(acc[mf][nf], al[mf], bh[nf]);
            }
    }

    // epilogue: relu(acc + bias)
#pragma unroll
    for (int nf = 0; nf < 4; nf++) {
        int c = n0 + nf * 8 + 2 * tg;
        float2 b2 = *reinterpret_cast<const float2*>(&bes[c]);
#pragma unroll
        for (int mf = 0; mf < 2; mf++) {
            int r0 = e0 + m0 + mf * 16 + gid;
            float2 o0, o1;
            o0.x = fmaxf(acc[mf][nf][0] + b2.x, 0.f);
            o0.y = fmaxf(acc[mf][nf][1] + b2.y, 0.f);
            o1.x = fmaxf(acc[mf][nf][2] + b2.x, 0.f);
            o1.y = fmaxf(acc[mf][nf][3] + b2.y, 0.f);
            *reinterpret_cast<float2*>(&g_bufA[(size_t)r0 * HH + c]) = o0;
            *reinterpret_cast<float2*>(&g_bufA[(size_t)(r0 + 8) * HH + c]) = o1;
        }
    }
}

// ---------------- pooling + FFN + sigmoid ----------------
__global__ __launch_bounds__(256) void k_pool(const int* __restrict__ batch,
                                              const float* __restrict__ fW,
                                              const float* __restrict__ fb,
                                              float* __restrict__ out) {
    int g = (blockIdx.x * 256 + threadIdx.x) >> 5;
    int lane = threadIdx.x & 31;
    if (g >= GG) return;
    int s, e;
    {
        int lo = 0, hi = NN;
        while (lo < hi) { int mid = (lo + hi) >> 1; if (batch[mid] < g) lo = mid + 1; else hi = mid; }
        s = lo;
    }
    {
        int lo = s, hi = NN;
        while (lo < hi) { int mid = (lo + hi) >> 1; if (batch[mid] < g + 1) lo = mid + 1; else hi = mid; }
        e = lo;
    }
    float4 acc = make_float4(0.f, 0.f, 0.f, 0.f);
    for (int n = s; n < e; n++) {
        float4 v = reinterpret_cast<const float4*>(g_amsg)[(size_t)n * 32 + lane];
        acc.x += v.x; acc.y += v.y; acc.z += v.z; acc.w += v.w;
    }
    float4 w = reinterpret_cast<const float4*>(fW)[lane];
    float dot = acc.x * w.x + acc.y * w.y + acc.z * w.z + acc.w * w.w;
#pragma unroll
    for (int off = 16; off; off >>= 1) dot += __shfl_down_sync(0xffffffffu, dot, off);
    if (lane == 0) {
        int cnt = e - s;
        float c = (float)(cnt > 0 ? cnt : 1);
        float z = dot / c + fb[0];
        out[g] = 1.f / (1.f + expf(-z));
    }
}

// ---------------- launch ----------------
extern "C" void kernel_launch(void* const* d_in, const int* in_sizes, int n_in,
                              void* d_out, int out_size) {
    const float* x     = (const float*)d_in[0];
    const float* eat   = (const float*)d_in[1];
    const int*   eidx  = (const int*)d_in[2];
    const int*   batch = (const int*)d_in[3];
    const float* Wei   = (const float*)d_in[6];
    const float* bei   = (const float*)d_in[7];
    const float* convW = (const float*)d_in[8];
    const float* convb = (const float*)d_in[9];
    const float* gam   = (const float*)d_in[10];
    const float* bet   = (const float*)d_in[11];
    const float* rm    = (const float*)d_in[12];
    const float* rv    = (const float*)d_in[13];
    const float* fW    = (const float*)d_in[14];
    const float* fb    = (const float*)d_in[15];
    float* out = (float*)d_out;

    const int* row = eidx;
    const int* col = eidx + EE;

    cudaFuncSetAttribute(k_gemm, cudaFuncAttributeMaxDynamicSharedMemorySize, SMEM_GEMM);
    cudaFuncSetAttribute(k_edge_init, cudaFuncAttributeMaxDynamicSharedMemorySize, SMEM_EI);

    // CSR build (deterministic after sort)
    k_zero_cnt<<<(NN + 255) / 256, 256>>>();
    k_count<<<(EE + 255) / 256, 256>>>(col);
    k_scan<<<1, 1024>>>();
    k_scatter<<<(EE + 255) / 256, 256>>>(col);
    k_sortcsr<<<(NN + 255) / 256, 256>>>();

    // parameter prep
    k_prep_w<<<(DD * HH * 64 + 255) / 256, 256>>>(convW);
    k_prep_wei<<<(HH * 32 + 255) / 256, 256>>>(Wei);
    k_prep_bn<<<(DD * HH + 255) / 256, 256>>>(convb, gam, bet, rm, rv);

    // edge init -> bufA
    k_edge_init<<<EE / 64, 256, SMEM_EI>>>(x, eat, row, bei);

    // 15 DMPNN layers, ping-pong A<->B
    for (int d = 0; d < DD; d++) {
        int flip = d & 1;
        k_amsg<<<(NN * 32 + 255) / 256, 256>>>(flip);
        k_gemm<<<EE / 64, 256, SMEM_GEMM>>>(flip, d, row);
    }

    // final node aggregation from bufB, then pool+FFN
    k_amsg<<<(NN * 32 + 255) / 256, 256>>>(1);
    k_pool<<<(GG * 32 + 255) / 256, 256>>>(batch, fW, fb, out);
}